// round 9
// baseline (speedup 1.0000x reference)
#include <cuda_runtime.h>
#include <cuda_fp16.h>

// Problem constants (from reference)
#define IN_F    20000
#define OUT_F   3000
#define BATCH   8192
#define VB      8          // batch elems per thread in spmm
#define SPMM_T  128        // threads per spmm block -> 1024 batch per block
#define PHASE_B 1024       // batch per phase (t_in(k) -> spmm(k) pairing)

// Scratch (static __device__ globals; no runtime allocation)
__device__ __half g_xT[(size_t)IN_F * BATCH];   // 327 MB, x transposed to [col][batch], fp16
__device__ float  g_yT[(size_t)OUT_F * BATCH];  //  98 MB, y transposed [row][batch], fp32
__device__ int    g_rowptr[OUT_F + 1];

// ---------------------------------------------------------------------------
// 1) CSR row pointers: rows[] sorted ascending -> row_ptr[r] = lower_bound.
// ---------------------------------------------------------------------------
__global__ void build_rowptr_kernel(const int* __restrict__ rows, int nnz) {
    int r = blockIdx.x * blockDim.x + threadIdx.x;
    if (r > OUT_F) return;
    int lo = 0, hi = nnz;
    while (lo < hi) {
        int mid = (lo + hi) >> 1;
        if (rows[mid] < r) lo = mid + 1; else hi = mid;
    }
    g_rowptr[r] = lo;
}

// ---------------------------------------------------------------------------
// 2) Transpose + convert (phased): x[b][c] fp32 -> g_xT[c][b] fp16.
//    Block: 32 cols x 128 batch = two 32x64 sub-tiles; 4 independent float4
//    LDGs per thread issued up front (MLP 4), then 2 uint4 fp16 stores.
// ---------------------------------------------------------------------------
__global__ void __launch_bounds__(256) transpose_in_kernel(
    const float* __restrict__ x, int b_base)
{
    __shared__ __align__(16) float tileA[32][65];
    __shared__ __align__(16) float tileB[32][65];
    const int c0 = blockIdx.x * 32;
    const int b0 = b_base + blockIdx.y * 128;
    const int t  = threadIdx.x;

    const int tx = t & 7;         // c-group (4 cols)
    const int ty = t >> 3;        // b-row within sub-tile half
    const size_t cbase = (size_t)c0 + tx * 4;

    // 4 independent global loads, issued back-to-back
    const float4 va0 = *reinterpret_cast<const float4*>(&x[(size_t)(b0 +       ty) * IN_F + cbase]);
    const float4 va1 = *reinterpret_cast<const float4*>(&x[(size_t)(b0 + 32  + ty) * IN_F + cbase]);
    const float4 vb0 = *reinterpret_cast<const float4*>(&x[(size_t)(b0 + 64  + ty) * IN_F + cbase]);
    const float4 vb1 = *reinterpret_cast<const float4*>(&x[(size_t)(b0 + 96  + ty) * IN_F + cbase]);

    tileA[tx * 4 + 0][ty]      = va0.x;  tileA[tx * 4 + 1][ty]      = va0.y;
    tileA[tx * 4 + 2][ty]      = va0.z;  tileA[tx * 4 + 3][ty]      = va0.w;
    tileA[tx * 4 + 0][ty + 32] = va1.x;  tileA[tx * 4 + 1][ty + 32] = va1.y;
    tileA[tx * 4 + 2][ty + 32] = va1.z;  tileA[tx * 4 + 3][ty + 32] = va1.w;
    tileB[tx * 4 + 0][ty]      = vb0.x;  tileB[tx * 4 + 1][ty]      = vb0.y;
    tileB[tx * 4 + 2][ty]      = vb0.z;  tileB[tx * 4 + 3][ty]      = vb0.w;
    tileB[tx * 4 + 0][ty + 32] = vb1.x;  tileB[tx * 4 + 1][ty + 32] = vb1.y;
    tileB[tx * 4 + 2][ty + 32] = vb1.z;  tileB[tx * 4 + 3][ty + 32] = vb1.w;
    __syncthreads();

    const int c  = t >> 3;        // 0..31
    const int bg = (t & 7) * 8;   // 0..56
    __half ha[8], hb[8];
    #pragma unroll
    for (int i = 0; i < 8; i++) ha[i] = __float2half(tileA[c][bg + i]);
    #pragma unroll
    for (int i = 0; i < 8; i++) hb[i] = __float2half(tileB[c][bg + i]);
    __half* dst = &g_xT[(size_t)(c0 + c) * BATCH + b0];
    *reinterpret_cast<uint4*>(dst + bg)      = *reinterpret_cast<const uint4*>(ha);
    *reinterpret_cast<uint4*>(dst + 64 + bg) = *reinterpret_cast<const uint4*>(hb);
}

// ---------------------------------------------------------------------------
// Packed helpers: half2 -> f32x2 (64-bit pair) and fma.rn.f32x2 (FFMA2).
// ---------------------------------------------------------------------------
__device__ __forceinline__ unsigned long long h2_to_f32x2(unsigned int h2) {
    unsigned long long r;
    asm("{\n\t"
        ".reg .f16 lo, hi;\n\t"
        ".reg .f32 a, b;\n\t"
        "mov.b32 {lo, hi}, %1;\n\t"
        "cvt.f32.f16 a, lo;\n\t"
        "cvt.f32.f16 b, hi;\n\t"
        "mov.b64 %0, {a, b};\n\t"
        "}" : "=l"(r) : "r"(h2));
    return r;
}

__device__ __forceinline__ void ffma2(unsigned long long& acc,
                                      unsigned long long xv,
                                      unsigned long long w2) {
    asm("fma.rn.f32x2 %0, %1, %2, %0;" : "+l"(acc) : "l"(xv), "l"(w2));
}

__device__ __forceinline__ unsigned long long bcast_f32x2(float w) {
    unsigned long long r;
    asm("mov.b64 %0, {%1, %1};" : "=l"(r) : "f"(w));
    return r;
}

__device__ __forceinline__ float2 unpack_f32x2(unsigned long long p) {
    float2 f;
    asm("mov.b64 {%0, %1}, %2;" : "=f"(f.x), "=f"(f.y) : "l"(p));
    return f;
}

// ---------------------------------------------------------------------------
// 3) SpMM (phased): block = one output row r over this phase's 1024 batch.
//    2 nnz per inner iter: 1 LDS.128 metadata + 2 LDG.128 x + 8 FFMA2.
//    xT tile for the phase is L2-resident (written by the paired t_in).
// ---------------------------------------------------------------------------
__global__ void __launch_bounds__(SPMM_T) spmm_kernel(
    const int* __restrict__ cols, const float* __restrict__ wts, int b_base)
{
    const int r  = blockIdx.x;
    const int t  = threadIdx.x;

    const int start = g_rowptr[r];
    const int end   = g_rowptr[r + 1];

    __shared__ __align__(16) int2 spk[SPMM_T + 2];   // {col, w bits}, +pad for dummy

    unsigned long long acc0 = 0ull, acc1 = 0ull, acc2 = 0ull, acc3 = 0ull;
    const int boff = b_base + t * VB;
    const __half* __restrict__ xT = g_xT;

    for (int j0 = start; j0 < end; j0 += SPMM_T) {
        const int n = min(SPMM_T, end - j0);
        int j = j0 + t;
        if (j < end) {
            int2 p;
            p.x = cols[j];
            p.y = __float_as_int(wts[j]);
            spk[t] = p;
        }
        if (t == 0 && (n & 1)) spk[n] = make_int2(0, 0);  // zero-weight dummy
        __syncthreads();
        const int n2 = (n + 1) & ~1;
        #pragma unroll 4
        for (int k = 0; k < n2; k += 2) {
            const int4 pp = *reinterpret_cast<const int4*>(&spk[k]);
            // nnz A
            {
                const unsigned long long w2 = bcast_f32x2(__int_as_float(pp.y));
                const uint4 v = *reinterpret_cast<const uint4*>(
                    &xT[(size_t)pp.x * BATCH + boff]);
                ffma2(acc0, h2_to_f32x2(v.x), w2);
                ffma2(acc1, h2_to_f32x2(v.y), w2);
                ffma2(acc2, h2_to_f32x2(v.z), w2);
                ffma2(acc3, h2_to_f32x2(v.w), w2);
            }
            // nnz B
            {
                const unsigned long long w2 = bcast_f32x2(__int_as_float(pp.w));
                const uint4 v = *reinterpret_cast<const uint4*>(
                    &xT[(size_t)pp.z * BATCH + boff]);
                ffma2(acc0, h2_to_f32x2(v.x), w2);
                ffma2(acc1, h2_to_f32x2(v.y), w2);
                ffma2(acc2, h2_to_f32x2(v.z), w2);
                ffma2(acc3, h2_to_f32x2(v.w), w2);
            }
        }
        __syncthreads();
    }

    const float2 f0 = unpack_f32x2(acc0);
    const float2 f1 = unpack_f32x2(acc1);
    const float2 f2 = unpack_f32x2(acc2);
    const float2 f3 = unpack_f32x2(acc3);
    float* yp = &g_yT[(size_t)r * BATCH + boff];
    *reinterpret_cast<float4*>(yp)     = make_float4(f0.x, f0.y, f1.x, f1.y);
    *reinterpret_cast<float4*>(yp + 4) = make_float4(f2.x, f2.y, f3.x, f3.y);
}

// ---------------------------------------------------------------------------
// 4) Transpose-out + bias: g_yT[r][b] -> out[b][r] + bias[r].  (unchanged)
// ---------------------------------------------------------------------------
__global__ void __launch_bounds__(256) transpose_out_kernel(
    const float* __restrict__ bias, float* __restrict__ out)
{
    __shared__ __align__(16) float tile[32][65];   // [r][b], pad 1
    const int r0 = blockIdx.x * 32;
    const int b0 = blockIdx.y * 64;
    const int t  = threadIdx.x;

    const int tx = t & 15;
    const int ty = t >> 4;
    #pragma unroll
    for (int i = 0; i < 2; i++) {
        const int rl = ty + 16 * i;
        const int r  = r0 + rl;
        float4 v = make_float4(0.f, 0.f, 0.f, 0.f);
        if (r < OUT_F)
            v = *reinterpret_cast<const float4*>(
                &g_yT[(size_t)r * BATCH + b0 + tx * 4]);
        tile[rl][tx * 4 + 0] = v.x;
        tile[rl][tx * 4 + 1] = v.y;
        tile[rl][tx * 4 + 2] = v.z;
        tile[rl][tx * 4 + 3] = v.w;
    }
    __syncthreads();

    const int bb = t >> 3;
    const int rr = (t & 7) * 4;
    const int rg = r0 + rr;

    float bx = 0.f, by = 0.f, bz = 0.f, bw = 0.f;
    if (rg + 0 < OUT_F) bx = bias[rg + 0];
    if (rg + 1 < OUT_F) by = bias[rg + 1];
    if (rg + 2 < OUT_F) bz = bias[rg + 2];
    if (rg + 3 < OUT_F) bw = bias[rg + 3];

    #pragma unroll
    for (int i = 0; i < 2; i++) {
        const int b = b0 + bb + 32 * i;
        float4 o;
        o.x = tile[rr + 0][bb + 32 * i] + bx;
        o.y = tile[rr + 1][bb + 32 * i] + by;
        o.z = tile[rr + 2][bb + 32 * i] + bz;
        o.w = tile[rr + 3][bb + 32 * i] + bw;
        if (rg + 3 < OUT_F) {
            *reinterpret_cast<float4*>(&out[(size_t)b * OUT_F + rg]) = o;
        } else {
            if (rg + 0 < OUT_F) out[(size_t)b * OUT_F + rg + 0] = o.x;
            if (rg + 1 < OUT_F) out[(size_t)b * OUT_F + rg + 1] = o.y;
            if (rg + 2 < OUT_F) out[(size_t)b * OUT_F + rg + 2] = o.z;
            if (rg + 3 < OUT_F) out[(size_t)b * OUT_F + rg + 3] = o.w;
        }
    }
}

// ---------------------------------------------------------------------------
// Launch. Inputs (metadata order): inputs f32 [8192*20000], weights f32 [nnz],
// bias f32 [3000], rows i32 [nnz], cols i32 [nnz]. Output f32 [8192*3000].
// Phase-paired: t_in(k) writes the 41 MB xT tile, spmm(k) consumes it while
// it is still L2-resident. Stream order guarantees correctness.
// ---------------------------------------------------------------------------
extern "C" void kernel_launch(void* const* d_in, const int* in_sizes, int n_in,
                              void* d_out, int out_size)
{
    const float* x    = (const float*)d_in[0];
    const float* wts  = (const float*)d_in[1];
    const float* bias = (const float*)d_in[2];
    const int*   rows = (const int*)  d_in[3];
    const int*   cols = (const int*)  d_in[4];
    const int    nnz  = in_sizes[1];
    float* out = (float*)d_out;

    build_rowptr_kernel<<<(OUT_F + 1 + 255) / 256, 256>>>(rows, nnz);
    for (int k = 0; k < BATCH / PHASE_B; k++) {
        transpose_in_kernel<<<dim3(IN_F / 32, PHASE_B / 128), 256>>>(x, k * PHASE_B);
        spmm_kernel<<<dim3(OUT_F), SPMM_T>>>(cols, wts, k * PHASE_B);
    }
    transpose_out_kernel<<<dim3((OUT_F + 31) / 32, BATCH / 64), 256>>>(bias, out);
}

// round 10
// speedup vs baseline: 1.2874x; 1.2874x over previous
#include <cuda_runtime.h>
#include <cuda_fp16.h>

// Problem constants (from reference)
#define IN_F    20000
#define OUT_F   3000
#define BATCH   8192
#define VB      8          // batch elems per thread in spmm
#define SPMM_T  128        // threads per spmm block -> 1024 batch per block

// Scratch (static __device__ globals; no runtime allocation)
__device__ __half g_xT[(size_t)IN_F * BATCH];   // 327 MB, x transposed to [col][batch], fp16
__device__ __half g_yT[(size_t)OUT_F * BATCH];  //  49 MB, y transposed [row][batch], fp16
__device__ int    g_rowptr[OUT_F + 1];

// ---------------------------------------------------------------------------
// 1) CSR row pointers: rows[] sorted ascending -> row_ptr[r] = lower_bound.
// ---------------------------------------------------------------------------
__global__ void build_rowptr_kernel(const int* __restrict__ rows, int nnz) {
    int r = blockIdx.x * blockDim.x + threadIdx.x;
    if (r > OUT_F) return;
    int lo = 0, hi = nnz;
    while (lo < hi) {
        int mid = (lo + hi) >> 1;
        if (rows[mid] < r) lo = mid + 1; else hi = mid;
    }
    g_rowptr[r] = lo;
}

// ---------------------------------------------------------------------------
// 2) Transpose + convert: x[b][c] fp32 -> g_xT[c][b] fp16.
//    Block: 32 cols x 128 batch = two 32x64 sub-tiles; 4 independent float4
//    LDGs per thread issued up front (MLP 4), then 2 uint4 fp16 stores.
// ---------------------------------------------------------------------------
__global__ void __launch_bounds__(256) transpose_in_kernel(const float* __restrict__ x)
{
    __shared__ __align__(16) float tileA[32][65];
    __shared__ __align__(16) float tileB[32][65];
    const int c0 = blockIdx.x * 32;
    const int b0 = blockIdx.y * 128;
    const int t  = threadIdx.x;

    const int tx = t & 7;         // c-group (4 cols)
    const int ty = t >> 3;        // b-row within sub-tile half
    const size_t cbase = (size_t)c0 + tx * 4;

    // 4 independent global loads, issued back-to-back
    const float4 va0 = *reinterpret_cast<const float4*>(&x[(size_t)(b0 +       ty) * IN_F + cbase]);
    const float4 va1 = *reinterpret_cast<const float4*>(&x[(size_t)(b0 + 32  + ty) * IN_F + cbase]);
    const float4 vb0 = *reinterpret_cast<const float4*>(&x[(size_t)(b0 + 64  + ty) * IN_F + cbase]);
    const float4 vb1 = *reinterpret_cast<const float4*>(&x[(size_t)(b0 + 96  + ty) * IN_F + cbase]);

    tileA[tx * 4 + 0][ty]      = va0.x;  tileA[tx * 4 + 1][ty]      = va0.y;
    tileA[tx * 4 + 2][ty]      = va0.z;  tileA[tx * 4 + 3][ty]      = va0.w;
    tileA[tx * 4 + 0][ty + 32] = va1.x;  tileA[tx * 4 + 1][ty + 32] = va1.y;
    tileA[tx * 4 + 2][ty + 32] = va1.z;  tileA[tx * 4 + 3][ty + 32] = va1.w;
    tileB[tx * 4 + 0][ty]      = vb0.x;  tileB[tx * 4 + 1][ty]      = vb0.y;
    tileB[tx * 4 + 2][ty]      = vb0.z;  tileB[tx * 4 + 3][ty]      = vb0.w;
    tileB[tx * 4 + 0][ty + 32] = vb1.x;  tileB[tx * 4 + 1][ty + 32] = vb1.y;
    tileB[tx * 4 + 2][ty + 32] = vb1.z;  tileB[tx * 4 + 3][ty + 32] = vb1.w;
    __syncthreads();

    const int c  = t >> 3;        // 0..31
    const int bg = (t & 7) * 8;   // 0..56
    __half ha[8], hb[8];
    #pragma unroll
    for (int i = 0; i < 8; i++) ha[i] = __float2half(tileA[c][bg + i]);
    #pragma unroll
    for (int i = 0; i < 8; i++) hb[i] = __float2half(tileB[c][bg + i]);
    __half* dst = &g_xT[(size_t)(c0 + c) * BATCH + b0];
    *reinterpret_cast<uint4*>(dst + bg)      = *reinterpret_cast<const uint4*>(ha);
    *reinterpret_cast<uint4*>(dst + 64 + bg) = *reinterpret_cast<const uint4*>(hb);
}

// ---------------------------------------------------------------------------
// Packed helpers: half2 -> f32x2 (64-bit pair) and fma.rn.f32x2 (FFMA2).
// ---------------------------------------------------------------------------
__device__ __forceinline__ unsigned long long h2_to_f32x2(unsigned int h2) {
    unsigned long long r;
    asm("{\n\t"
        ".reg .f16 lo, hi;\n\t"
        ".reg .f32 a, b;\n\t"
        "mov.b32 {lo, hi}, %1;\n\t"
        "cvt.f32.f16 a, lo;\n\t"
        "cvt.f32.f16 b, hi;\n\t"
        "mov.b64 %0, {a, b};\n\t"
        "}" : "=l"(r) : "r"(h2));
    return r;
}

__device__ __forceinline__ void ffma2(unsigned long long& acc,
                                      unsigned long long xv,
                                      unsigned long long w2) {
    asm("fma.rn.f32x2 %0, %1, %2, %0;" : "+l"(acc) : "l"(xv), "l"(w2));
}

__device__ __forceinline__ unsigned long long bcast_f32x2(float w) {
    unsigned long long r;
    asm("mov.b64 %0, {%1, %1};" : "=l"(r) : "f"(w));
    return r;
}

__device__ __forceinline__ float2 unpack_f32x2(unsigned long long p) {
    float2 f;
    asm("mov.b64 {%0, %1}, %2;" : "=f"(f.x), "=f"(f.y) : "l"(p));
    return f;
}

// ---------------------------------------------------------------------------
// 3) SpMM: block = (one output row r) x (1024-batch tile). Monolithic grid
//    (3000, 8), bid.x fastest -> each 41 MB xT batch-tile stays L2-resident.
//    2 nnz per inner iter: 1 LDS.128 metadata + 2 LDG.128 x + 8 FFMA2.
//    Output packed to fp16 -> single STG.128.
// ---------------------------------------------------------------------------
__global__ void __launch_bounds__(SPMM_T) spmm_kernel(
    const int* __restrict__ cols, const float* __restrict__ wts)
{
    const int r  = blockIdx.x;
    const int b0 = blockIdx.y * (SPMM_T * VB);
    const int t  = threadIdx.x;

    const int start = g_rowptr[r];
    const int end   = g_rowptr[r + 1];

    __shared__ __align__(16) int2 spk[SPMM_T + 2];   // {col, w bits}, +pad for dummy

    unsigned long long acc0 = 0ull, acc1 = 0ull, acc2 = 0ull, acc3 = 0ull;
    const int boff = b0 + t * VB;
    const __half* __restrict__ xT = g_xT;

    for (int j0 = start; j0 < end; j0 += SPMM_T) {
        const int n = min(SPMM_T, end - j0);
        int j = j0 + t;
        if (j < end) {
            int2 p;
            p.x = cols[j];
            p.y = __float_as_int(wts[j]);
            spk[t] = p;
        }
        if (t == 0 && (n & 1)) spk[n] = make_int2(0, 0);  // zero-weight dummy
        __syncthreads();
        const int n2 = (n + 1) & ~1;
        #pragma unroll 4
        for (int k = 0; k < n2; k += 2) {
            const int4 pp = *reinterpret_cast<const int4*>(&spk[k]);
            // nnz A
            {
                const unsigned long long w2 = bcast_f32x2(__int_as_float(pp.y));
                const uint4 v = *reinterpret_cast<const uint4*>(
                    &xT[(size_t)pp.x * BATCH + boff]);
                ffma2(acc0, h2_to_f32x2(v.x), w2);
                ffma2(acc1, h2_to_f32x2(v.y), w2);
                ffma2(acc2, h2_to_f32x2(v.z), w2);
                ffma2(acc3, h2_to_f32x2(v.w), w2);
            }
            // nnz B
            {
                const unsigned long long w2 = bcast_f32x2(__int_as_float(pp.w));
                const uint4 v = *reinterpret_cast<const uint4*>(
                    &xT[(size_t)pp.z * BATCH + boff]);
                ffma2(acc0, h2_to_f32x2(v.x), w2);
                ffma2(acc1, h2_to_f32x2(v.y), w2);
                ffma2(acc2, h2_to_f32x2(v.z), w2);
                ffma2(acc3, h2_to_f32x2(v.w), w2);
            }
        }
        __syncthreads();
    }

    const float2 f0 = unpack_f32x2(acc0);
    const float2 f1 = unpack_f32x2(acc1);
    const float2 f2 = unpack_f32x2(acc2);
    const float2 f3 = unpack_f32x2(acc3);
    __half2 o[4];
    o[0] = __floats2half2_rn(f0.x, f0.y);
    o[1] = __floats2half2_rn(f1.x, f1.y);
    o[2] = __floats2half2_rn(f2.x, f2.y);
    o[3] = __floats2half2_rn(f3.x, f3.y);
    *reinterpret_cast<uint4*>(&g_yT[(size_t)r * BATCH + boff]) =
        *reinterpret_cast<const uint4*>(o);
}

// ---------------------------------------------------------------------------
// 4) Transpose-out + bias: g_yT[r][b] fp16 -> out[b][r] fp32 + bias[r].
// ---------------------------------------------------------------------------
__global__ void __launch_bounds__(256) transpose_out_kernel(
    const float* __restrict__ bias, float* __restrict__ out)
{
    __shared__ __align__(16) float tile[32][65];   // [r][b], pad 1
    const int r0 = blockIdx.x * 32;
    const int b0 = blockIdx.y * 64;
    const int t  = threadIdx.x;

    const int tx = t & 15;
    const int ty = t >> 4;
    #pragma unroll
    for (int i = 0; i < 2; i++) {
        const int rl = ty + 16 * i;
        const int r  = r0 + rl;
        float2 p0 = make_float2(0.f, 0.f), p1 = make_float2(0.f, 0.f);
        if (r < OUT_F) {
            const uint2 h4 = *reinterpret_cast<const uint2*>(
                &g_yT[(size_t)r * BATCH + b0 + tx * 4]);
            p0 = __half22float2(*reinterpret_cast<const half2*>(&h4.x));
            p1 = __half22float2(*reinterpret_cast<const half2*>(&h4.y));
        }
        tile[rl][tx * 4 + 0] = p0.x;
        tile[rl][tx * 4 + 1] = p0.y;
        tile[rl][tx * 4 + 2] = p1.x;
        tile[rl][tx * 4 + 3] = p1.y;
    }
    __syncthreads();

    const int bb = t >> 3;
    const int rr = (t & 7) * 4;
    const int rg = r0 + rr;

    float bx = 0.f, by = 0.f, bz = 0.f, bw = 0.f;
    if (rg + 0 < OUT_F) bx = bias[rg + 0];
    if (rg + 1 < OUT_F) by = bias[rg + 1];
    if (rg + 2 < OUT_F) bz = bias[rg + 2];
    if (rg + 3 < OUT_F) bw = bias[rg + 3];

    #pragma unroll
    for (int i = 0; i < 2; i++) {
        const int b = b0 + bb + 32 * i;
        float4 o;
        o.x = tile[rr + 0][bb + 32 * i] + bx;
        o.y = tile[rr + 1][bb + 32 * i] + by;
        o.z = tile[rr + 2][bb + 32 * i] + bz;
        o.w = tile[rr + 3][bb + 32 * i] + bw;
        if (rg + 3 < OUT_F) {
            *reinterpret_cast<float4*>(&out[(size_t)b * OUT_F + rg]) = o;
        } else {
            if (rg + 0 < OUT_F) out[(size_t)b * OUT_F + rg + 0] = o.x;
            if (rg + 1 < OUT_F) out[(size_t)b * OUT_F + rg + 1] = o.y;
            if (rg + 2 < OUT_F) out[(size_t)b * OUT_F + rg + 2] = o.z;
            if (rg + 3 < OUT_F) out[(size_t)b * OUT_F + rg + 3] = o.w;
        }
    }
}

// ---------------------------------------------------------------------------
// Launch. Inputs (metadata order): inputs f32 [8192*20000], weights f32 [nnz],
// bias f32 [3000], rows i32 [nnz], cols i32 [nnz]. Output f32 [8192*3000].
// ---------------------------------------------------------------------------
extern "C" void kernel_launch(void* const* d_in, const int* in_sizes, int n_in,
                              void* d_out, int out_size)
{
    const float* x    = (const float*)d_in[0];
    const float* wts  = (const float*)d_in[1];
    const float* bias = (const float*)d_in[2];
    const int*   rows = (const int*)  d_in[3];
    const int*   cols = (const int*)  d_in[4];
    const int    nnz  = in_sizes[1];
    float* out = (float*)d_out;

    build_rowptr_kernel<<<(OUT_F + 1 + 255) / 256, 256>>>(rows, nnz);
    transpose_in_kernel<<<dim3(IN_F / 32, BATCH / 128), 256>>>(x);
    spmm_kernel<<<dim3(OUT_F, BATCH / (SPMM_T * VB)), SPMM_T>>>(cols, wts);
    transpose_out_kernel<<<dim3((OUT_F + 31) / 32, BATCH / 64), 256>>>(bias, out);
}